// round 9
// baseline (speedup 1.0000x reference)
#include <cuda_runtime.h>

#define TT 512
#define BB 512
#define KK 64
#define STRD (BB*KK)
#define LOG2E 1.4426950408889634f
#define LN2   0.6931471805599453f

typedef unsigned long long ull;

// scratch (device globals — no allocation)
__device__ float g_partial[BB];
__device__ int   g_cntp[64];   // detect partials, plain-stored each replay
__device__ int   g_done;       // reset by detect block 0 each replay

__device__ __forceinline__ float ex2f_(float x){float y;asm("ex2.approx.f32 %0,%1;":"=f"(y):"f"(x));return y;}
__device__ __forceinline__ float lg2f_(float x){float y;asm("lg2.approx.f32 %0,%1;":"=f"(y):"f"(x));return y;}
__device__ __forceinline__ float rcpf_(float x){float y;asm("rcp.approx.f32 %0,%1;":"=f"(y):"f"(x));return y;}
__device__ __forceinline__ ull fma2_(ull a,ull b,ull c){ull d;asm("fma.rn.f32x2 %0,%1,%2,%3;":"=l"(d):"l"(a),"l"(b),"l"(c));return d;}
__device__ __forceinline__ ull add2_(ull a,ull b){ull d;asm("add.rn.f32x2 %0,%1,%2;":"=l"(d):"l"(a),"l"(b));return d;}
__device__ __forceinline__ ull pack2_(float lo,float hi){ull d;asm("mov.b64 %0,{%1,%2};":"=l"(d):"f"(lo),"f"(hi));return d;}
__device__ __forceinline__ float2 unpack2_(ull v){float2 r;asm("mov.b64 {%0,%1},%2;":"=f"(r.x),"=f"(r.y):"l"(v));return r;}

#define CNTB(u) ((((u)&0xFFu)!=0)+(((u)&0xFF00u)!=0)+(((u)&0xFF0000u)!=0)+(((u)&0xFF000000u)!=0))

// ---------------------------------------------------------------------------
// Detect: 64 blocks x 256 threads, one uint4 per thread over the first TT*BB
// bytes of the mask (safe under bool/int32/f32 serializations). A 1-byte
// one-hot mask has exactly BB nonzero bytes total. Plain stores: idempotent
// across graph replays. Block 0 also resets the forward completion counter.
// ---------------------------------------------------------------------------
__global__ __launch_bounds__(256) void detect_kernel(const unsigned char* __restrict__ m)
{
    __shared__ int w_s[8];
    const int tid = threadIdx.x;
    if (blockIdx.x == 0 && tid == 0) g_done = 0;
    uint4 v = ((const uint4*)m)[blockIdx.x * 256 + tid];
    int local = CNTB(v.x) + CNTB(v.y) + CNTB(v.z) + CNTB(v.w);
    #pragma unroll
    for (int o = 16; o > 0; o >>= 1) local += __shfl_xor_sync(0xffffffffu, local, o);
    if ((tid & 31) == 0) w_s[tid >> 5] = local;
    __syncthreads();
    if (tid == 0) {
        int s = 0;
        #pragma unroll
        for (int k = 0; k < 8; k++) s += w_s[k];
        g_cntp[blockIdx.x] = s;
    }
}

// ---------------------------------------------------------------------------
// Forward: 256 CTAs x 128 threads. Group g = tid>>6 (warps {0,1} / {2,3},
// i.e. SMSPs {0,1} / {2,3}) independently runs batch b = 2*blockIdx.x + g,
// synchronized ONLY by its own named barrier (bar.sync 1+g, 64). This uses
// all 4 SMSPs per SM (64-thread blocks left SMSPs 2,3 idle chip-wide).
// Per-group recurrence (thread j owns state-column j), register-local pivot:
//   S_j  = sum_i P_i * E_ij      (E = exp(trans), column j packed f32x2)
//   c    = rcp(P_0^{t-1}) ;  C2 += lg2(P_0^{t-1})   (hidden under the burst)
//   P'_j = S_j * em_j * c
// Invariant: log2 alpha_j = lg2(P_j) + C2 (exact).
// Final per-b: LN2 * (C2 + lg2(sum_j P_j)). Last-arriving group does 512->1.
// ---------------------------------------------------------------------------
__global__ __launch_bounds__(128, 4)
void crf_forward_kernel(const float* __restrict__ emits,
                        const unsigned char* __restrict__ mask,
                        const float* __restrict__ trans,
                        const float* __restrict__ alpha0,
                        float* __restrict__ out)
{
    __shared__ float p_s[2][2][KK];   // [g][buf][j]
    __shared__ float red_s[2][2];     // [g][warp-in-group]
    __shared__ int   stop_sh[2];
    __shared__ int   is4_sh;
    __shared__ int   last_sh[2];

    const int tid = threadIdx.x;
    const int g   = tid >> 6;          // group 0: warps 0,1 ; group 1: warps 2,3
    const int j   = tid & 63;          // state column
    const int b   = 2 * blockIdx.x + g;
    const int gbar = 1 + g;            // named barrier id for this group

#define GBAR() asm volatile("bar.sync %0, 64;" :: "r"(gbar) : "memory")

    if (tid < 2) stop_sh[tid] = 0;

    // mask dtype: warp 0 sums the 64 detect partials
    if (tid < 32) {
        int c0 = g_cntp[tid] + g_cntp[tid + 32];
        #pragma unroll
        for (int o = 16; o > 0; o >>= 1) c0 += __shfl_xor_sync(0xffffffffu, c0, o);
        if (tid == 0) is4_sh = (c0 != BB);
    }
    __syncthreads();
    const bool is4 = is4_sh;

    // stop index for batch b: 64 threads of the group scan; one-hot => one atomic
    if (is4) {
        const unsigned* m4 = (const unsigned*)mask;
        #pragma unroll
        for (int k = 0; k < TT / KK; k++) {
            int t = j + KK * k;
            if (m4[t * BB + b]) atomicMax(&stop_sh[g], t);
        }
    } else {
        #pragma unroll
        for (int k = 0; k < TT / KK; k++) {
            int t = j + KK * k;
            if (mask[t * BB + b]) atomicMax(&stop_sh[g], t);
        }
    }

    // E = exp(trans) column j, packed over i-pairs (register-resident)
    ull tr2[KK / 2];
    #pragma unroll
    for (int m = 0; m < KK / 2; m++)
        tr2[m] = pack2_(ex2f_(trans[(2*m  )*KK + j] * LOG2E),
                        ex2f_(trans[(2*m+1)*KK + j] * LOG2E));

    __syncthreads();
    const int stop = stop_sh[g];       // uniform within group

    const float* ep = emits + b * KK + j;
    float P = ex2f_((alpha0[j] + ep[0]) * LOG2E);
    p_s[g][0][j] = P;
    float C2 = 0.f;

    // emit pipeline depth 4: em = converted emit(t); r1..r3 = raw emit(t+1..t+3)
    float em = ex2f_(ep[min(1, stop) * STRD] * LOG2E);
    float r1 = ep[min(2, stop) * STRD];
    float r2 = ep[min(3, stop) * STRD];
    float r3 = ep[min(4, stop) * STRD];
    const float* pld = ep + (long)min(5, stop) * STRD;

    GBAR();

    // One recurrence step: read p_s[g][RB], write p_s[g][WB]. Static indices.
#define CRF_STEP(RB, WB, TCUR)                                                 \
    {                                                                          \
        const float ld = *pld;                       /* prefetch emit(t+4) */  \
        if ((TCUR) + 5 <= stop) pld += STRD;                                   \
        const ulonglong2* p2 = (const ulonglong2*)p_s[g][RB];                  \
        ulonglong2 v0 = p2[0];                                                 \
        const float p0prev = unpack2_(v0.x).x;                                 \
        const float c = rcpf_(p0prev);               /* hidden under burst */  \
        C2 += lg2f_(p0prev);                                                   \
        const float emc = em * c;                                              \
        ull a0 = fma2_(v0.x, tr2[0], 0ull);                                    \
        ull a1 = fma2_(v0.y, tr2[1], 0ull);                                    \
        ulonglong2 w0 = p2[1];                                                 \
        ull a2 = fma2_(w0.x, tr2[2], 0ull);                                    \
        ull a3 = fma2_(w0.y, tr2[3], 0ull);                                    \
        _Pragma("unroll")                                                      \
        for (int i = 1; i < 8; i++) {                                          \
            ulonglong2 v = p2[2*i], w = p2[2*i+1];                             \
            a0 = fma2_(v.x, tr2[4*i+0], a0);                                   \
            a1 = fma2_(v.y, tr2[4*i+1], a1);                                   \
            a2 = fma2_(w.x, tr2[4*i+2], a2);                                   \
            a3 = fma2_(w.y, tr2[4*i+3], a3);                                   \
        }                                                                      \
        float2 f = unpack2_(add2_(add2_(a0, a1), add2_(a2, a3)));              \
        const float S = f.x + f.y;                                             \
        P = S * emc;                                                           \
        p_s[g][WB][j] = P;                                                     \
        em = ex2f_(r1 * LOG2E);                      /* off-chain MUFU */      \
        r1 = r2; r2 = r3; r3 = ld;                                             \
        GBAR();                                                                \
    }

    int t = 1;
    for (; t + 1 <= stop; t += 2) {
        CRF_STEP(0, 1, t)
        CRF_STEP(1, 0, t + 1)
    }
    if (t <= stop) CRF_STEP(0, 1, t)
#undef CRF_STEP

    // per-b sum over states -> logZ_b (group-local)
    float v = P;
    #pragma unroll
    for (int o = 16; o > 0; o >>= 1) v += __shfl_xor_sync(0xffffffffu, v, o);
    if ((j & 31) == 0) red_s[g][j >> 5] = v;
    GBAR();
    if (j == 0) {
        g_partial[b] = LN2 * (C2 + lg2f_(red_s[g][0] + red_s[g][1]));
        __threadfence();
        last_sh[g] = (atomicAdd(&g_done, 1) == BB - 1);
    }
    GBAR();

    if (last_sh[g]) {                  // deterministic 512->1 sum by last group
        __threadfence();
        float s = 0.f;
        #pragma unroll
        for (int k = 0; k < BB / KK; k++) s += g_partial[j + k * KK];
        #pragma unroll
        for (int o = 16; o > 0; o >>= 1) s += __shfl_xor_sync(0xffffffffu, s, o);
        if ((j & 31) == 0) red_s[g][j >> 5] = s;
        GBAR();
        if (j == 0) out[0] = red_s[g][0] + red_s[g][1];
    }
#undef GBAR
}

extern "C" void kernel_launch(void* const* d_in, const int* in_sizes, int n_in,
                              void* d_out, int out_size)
{
    // Identify inputs by element count (robust to metadata ordering):
    // emits 16777216, mask 262144, trans 4096, alpha0 64.
    const float*         emits  = 0;
    const unsigned char* mask   = 0;
    const float*         trans  = 0;
    const float*         alpha0 = 0;
    for (int i = 0; i < n_in; i++) {
        switch (in_sizes[i]) {
            case 16777216: emits  = (const float*)d_in[i];         break;
            case   262144: mask   = (const unsigned char*)d_in[i]; break;
            case     4096: trans  = (const float*)d_in[i];         break;
            case       64: alpha0 = (const float*)d_in[i];         break;
        }
    }
    detect_kernel<<<64, 256>>>(mask);
    crf_forward_kernel<<<BB / 2, 128>>>(emits, mask, trans, alpha0, (float*)d_out);
}

// round 10
// speedup vs baseline: 1.1346x; 1.1346x over previous
#include <cuda_runtime.h>

#define TT 512
#define BB 512
#define KK 64
#define STRD (BB*KK)
#define LOG2E 1.4426950408889634f
#define LN2   0.6931471805599453f

typedef unsigned long long ull;

// scratch (device globals — no allocation)
__device__ float g_partial[BB];
__device__ int   g_cntp[64];   // detect partials, plain-stored each replay
__device__ int   g_done;       // reset by detect block 0 each replay

__device__ __forceinline__ float ex2f_(float x){float y;asm("ex2.approx.f32 %0,%1;":"=f"(y):"f"(x));return y;}
__device__ __forceinline__ float lg2f_(float x){float y;asm("lg2.approx.f32 %0,%1;":"=f"(y):"f"(x));return y;}
__device__ __forceinline__ float rcpf_(float x){float y;asm("rcp.approx.f32 %0,%1;":"=f"(y):"f"(x));return y;}
__device__ __forceinline__ ull fma2_(ull a,ull b,ull c){ull d;asm("fma.rn.f32x2 %0,%1,%2,%3;":"=l"(d):"l"(a),"l"(b),"l"(c));return d;}
__device__ __forceinline__ ull add2_(ull a,ull b){ull d;asm("add.rn.f32x2 %0,%1,%2;":"=l"(d):"l"(a),"l"(b));return d;}
__device__ __forceinline__ ull pack2_(float lo,float hi){ull d;asm("mov.b64 %0,{%1,%2};":"=l"(d):"f"(lo),"f"(hi));return d;}
__device__ __forceinline__ float2 unpack2_(ull v){float2 r;asm("mov.b64 {%0,%1},%2;":"=f"(r.x),"=f"(r.y):"l"(v));return r;}

#define CNTB(u) ((((u)&0xFFu)!=0)+(((u)&0xFF00u)!=0)+(((u)&0xFF0000u)!=0)+(((u)&0xFF000000u)!=0))

// ---------------------------------------------------------------------------
// Detect: 64 blocks x 256 threads, one uint4 per thread over the first TT*BB
// bytes of the mask (safe under bool/int32/f32 serializations). A 1-byte
// one-hot mask has exactly BB nonzero bytes total. Plain stores: idempotent
// across graph replays. Block 0 also resets the forward completion counter.
// ---------------------------------------------------------------------------
__global__ __launch_bounds__(256) void detect_kernel(const unsigned char* __restrict__ m)
{
    __shared__ int w_s[8];
    const int tid = threadIdx.x;
    if (blockIdx.x == 0 && tid == 0) g_done = 0;
    uint4 v = ((const uint4*)m)[blockIdx.x * 256 + tid];
    int local = CNTB(v.x) + CNTB(v.y) + CNTB(v.z) + CNTB(v.w);
    #pragma unroll
    for (int o = 16; o > 0; o >>= 1) local += __shfl_xor_sync(0xffffffffu, local, o);
    if ((tid & 31) == 0) w_s[tid >> 5] = local;
    __syncthreads();
    if (tid == 0) {
        int s = 0;
        #pragma unroll
        for (int k = 0; k < 8; k++) s += w_s[k];
        g_cntp[blockIdx.x] = s;
    }
}

// ---------------------------------------------------------------------------
// Forward: one CTA (64 threads = 2 warps) per batch element b; thread j owns
// state-column j. Linear-domain recurrence, register-local pivot renorm:
//   S_j  = sum_i P_i * E_ij      (E = exp(trans), column j packed f32x2 over i)
//   c    = rcp(P_0^{t-1})        (P_0 read from the thread's own first LDS.128)
//   P'_j = S_j * em_j * c ;  C2 += lg2(P_0^{t-1})   (both hidden under burst)
// Invariant: log2 alpha_j = lg2(P_j) + C2 (exact).
// t-loop unrolled x4, static buffer roles, emit registers rotated explicitly;
// the ex2 emit conversion sits AFTER the barrier (private regs — not blocked
// by DEFER_BLOCKING), hiding under next step's LDS shadow.
// Final per-b: LN2 * (C2 + lg2(sum_j P_j)). Last-arriving CTA does 512->1 sum.
// ---------------------------------------------------------------------------
__global__ __launch_bounds__(KK, 8)
void crf_forward_kernel(const float* __restrict__ emits,
                        const unsigned char* __restrict__ mask,
                        const float* __restrict__ trans,
                        const float* __restrict__ alpha0,
                        float* __restrict__ out)
{
    __shared__ float p_s[2][KK];
    __shared__ float red_s[2];
    __shared__ int   stop_sh;
    __shared__ int   is4_sh;
    __shared__ int   last_s;

    const int j = threadIdx.x;
    const int b = blockIdx.x;

    if (j == 0) stop_sh = 0;

    // mask dtype: sum the 64 detect partials (warp0 lanes load one each)
    if (j < 32) {
        int c0 = g_cntp[j] + g_cntp[j + 32];
        #pragma unroll
        for (int o = 16; o > 0; o >>= 1) c0 += __shfl_xor_sync(0xffffffffu, c0, o);
        if (j == 0) is4_sh = (c0 != BB);
    }
    __syncthreads();
    const bool is4 = is4_sh;

    // stop index: one-hot => exactly one thread fires the atomic
    if (is4) {
        const unsigned* m4 = (const unsigned*)mask;
        #pragma unroll
        for (int k = 0; k < TT / KK; k++) {
            int t = j + KK * k;
            if (m4[t * BB + b]) atomicMax(&stop_sh, t);
        }
    } else {
        #pragma unroll
        for (int k = 0; k < TT / KK; k++) {
            int t = j + KK * k;
            if (mask[t * BB + b]) atomicMax(&stop_sh, t);
        }
    }

    // E = exp(trans) column j, packed over i-pairs (register-resident)
    ull tr2[KK / 2];
    #pragma unroll
    for (int m = 0; m < KK / 2; m++)
        tr2[m] = pack2_(ex2f_(trans[(2*m  )*KK + j] * LOG2E),
                        ex2f_(trans[(2*m+1)*KK + j] * LOG2E));

    __syncthreads();
    const int stop = stop_sh;   // uniform

    const float* ep = emits + b * KK + j;
    float P = ex2f_((alpha0[j] + ep[0]) * LOG2E);
    p_s[0][j] = P;
    float C2 = 0.f;

    // emit pipeline depth 4: em = converted emit(t); rA,rB,rC = raw emit(t+1..t+3)
    float em = ex2f_(ep[min(1, stop) * STRD] * LOG2E);
    float rA = ep[min(2, stop) * STRD];
    float rB = ep[min(3, stop) * STRD];
    float rC = ep[min(4, stop) * STRD];

    __syncthreads();

    // One recurrence step. Read p_s[RB], write p_s[WB] (static indices).
    // EMIT = converted emit(t). LDREG receives raw emit(t+4) (min-clamped: a
    // clamped read duplicates emit(stop), which is never consumed since step
    // u>stop doesn't run). NEWEM = ex2 of raw emit(t+1), issued AFTER the bar.
#define CRF_STEP(RB, WB, TCUR, EMIT, RNEXT, LDREG, NEWEM)                      \
    {                                                                          \
        const float LDREG = ep[(long)min((TCUR) + 4, stop) * STRD];            \
        const ulonglong2* p2 = (const ulonglong2*)p_s[RB];                     \
        ulonglong2 v0 = p2[0];                                                 \
        const float p0prev = unpack2_(v0.x).x;                                 \
        const float c = rcpf_(p0prev);               /* hidden under burst */  \
        C2 += lg2f_(p0prev);                                                   \
        const float emc = (EMIT) * c;                                          \
        ull a0 = fma2_(v0.x, tr2[0], 0ull);                                    \
        ull a1 = fma2_(v0.y, tr2[1], 0ull);                                    \
        ulonglong2 w0 = p2[1];                                                 \
        ull a2 = fma2_(w0.x, tr2[2], 0ull);                                    \
        ull a3 = fma2_(w0.y, tr2[3], 0ull);                                    \
        _Pragma("unroll")                                                      \
        for (int i = 1; i < 8; i++) {                                          \
            ulonglong2 v = p2[2*i], w = p2[2*i+1];                             \
            a0 = fma2_(v.x, tr2[4*i+0], a0);                                   \
            a1 = fma2_(v.y, tr2[4*i+1], a1);                                   \
            a2 = fma2_(w.x, tr2[4*i+2], a2);                                   \
            a3 = fma2_(w.y, tr2[4*i+3], a3);                                   \
        }                                                                      \
        float2 f = unpack2_(add2_(add2_(a0, a1), add2_(a2, a3)));              \
        const float S = f.x + f.y;                                             \
        P = S * emc;                                                           \
        p_s[WB][j] = P;                                                        \
        __syncthreads();                                                       \
        const float NEWEM = ex2f_((RNEXT) * LOG2E);  /* post-bar: private */   \
        (void)NEWEM;

#define CRF_END }

    int t = 1;
    for (; t + 3 <= stop; t += 4) {
        CRF_STEP(0, 1, t,     em,  rA, ld0, em1)     // consumes em,    stages em1
        CRF_STEP(1, 0, t + 1, em1, rB, ld1, em2)     // consumes em1
        CRF_STEP(0, 1, t + 2, em2, rC, ld2, em3)
        CRF_STEP(1, 0, t + 3, em3, ld0, ld3, em4)    // em for next block from ld0
        em = em4; rA = ld1; rB = ld2; rC = ld3;      // rotate (3 movs / 4 steps)
        CRF_END CRF_END CRF_END CRF_END
    }
    // epilogue: up to 3 leftover steps, alternating buffers from parity of t
    for (; t <= stop; t++) {
        if ((t & 1) == 1) {  // after main loop t is odd-first pattern: t started at 1
            CRF_STEP(0, 1, t, em, rA, lde, eme)
            em = eme; rA = rB; rB = rC; rC = lde;
            CRF_END
        } else {
            CRF_STEP(1, 0, t, em, rA, lde, eme)
            em = eme; rA = rB; rB = rC; rC = lde;
            CRF_END
        }
    }
#undef CRF_STEP
#undef CRF_END

    // per-b sum over states -> logZ_b
    float v = P;
    #pragma unroll
    for (int o = 16; o > 0; o >>= 1) v += __shfl_xor_sync(0xffffffffu, v, o);
    if ((j & 31) == 0) red_s[j >> 5] = v;
    __syncthreads();
    if (j == 0) {
        g_partial[b] = LN2 * (C2 + lg2f_(red_s[0] + red_s[1]));
        __threadfence();
        last_s = (atomicAdd(&g_done, 1) == BB - 1);
    }
    __syncthreads();

    if (last_s) {                                    // deterministic 512->1 sum
        __threadfence();
        float s = 0.f;
        #pragma unroll
        for (int k = 0; k < BB / KK; k++) s += g_partial[j + k * KK];
        #pragma unroll
        for (int o = 16; o > 0; o >>= 1) s += __shfl_xor_sync(0xffffffffu, s, o);
        if ((j & 31) == 0) red_s[j >> 5] = s;
        __syncthreads();
        if (j == 0) out[0] = red_s[0] + red_s[1];
    }
}

extern "C" void kernel_launch(void* const* d_in, const int* in_sizes, int n_in,
                              void* d_out, int out_size)
{
    // Identify inputs by element count (robust to metadata ordering):
    // emits 16777216, mask 262144, trans 4096, alpha0 64.
    const float*         emits  = 0;
    const unsigned char* mask   = 0;
    const float*         trans  = 0;
    const float*         alpha0 = 0;
    for (int i = 0; i < n_in; i++) {
        switch (in_sizes[i]) {
            case 16777216: emits  = (const float*)d_in[i];         break;
            case   262144: mask   = (const unsigned char*)d_in[i]; break;
            case     4096: trans  = (const float*)d_in[i];         break;
            case       64: alpha0 = (const float*)d_in[i];         break;
        }
    }
    detect_kernel<<<64, 256>>>(mask);
    crf_forward_kernel<<<BB, KK>>>(emits, mask, trans, alpha0, (float*)d_out);
}

// round 11
// speedup vs baseline: 1.1518x; 1.0152x over previous
#include <cuda_runtime.h>

#define TT 512
#define BB 512
#define KK 64
#define STRD (BB*KK)
#define LOG2E 1.4426950408889634f
#define LN2   0.6931471805599453f

typedef unsigned long long ull;

// scratch (device globals — no allocation)
__device__ float g_partial[BB];
__device__ int   g_cntp[64];   // detect partials, plain-stored each replay
__device__ int   g_done;       // reset by detect block 0 each replay

__device__ __forceinline__ float ex2f_(float x){float y;asm("ex2.approx.f32 %0,%1;":"=f"(y):"f"(x));return y;}
__device__ __forceinline__ float lg2f_(float x){float y;asm("lg2.approx.f32 %0,%1;":"=f"(y):"f"(x));return y;}
__device__ __forceinline__ ull fma2_(ull a,ull b,ull c){ull d;asm("fma.rn.f32x2 %0,%1,%2,%3;":"=l"(d):"l"(a),"l"(b),"l"(c));return d;}
__device__ __forceinline__ ull add2_(ull a,ull b){ull d;asm("add.rn.f32x2 %0,%1,%2;":"=l"(d):"l"(a),"l"(b));return d;}
__device__ __forceinline__ ull pack2_(float lo,float hi){ull d;asm("mov.b64 %0,{%1,%2};":"=l"(d):"f"(lo),"f"(hi));return d;}
__device__ __forceinline__ float2 unpack2_(ull v){float2 r;asm("mov.b64 {%0,%1},%2;":"=f"(r.x),"=f"(r.y):"l"(v));return r;}

#define CNTB(u) ((((u)&0xFFu)!=0)+(((u)&0xFF00u)!=0)+(((u)&0xFF0000u)!=0)+(((u)&0xFF000000u)!=0))

// ---------------------------------------------------------------------------
// Detect: 64 blocks x 256 threads, one uint4 per thread over the first TT*BB
// bytes of the mask (safe under bool/int32/f32 serializations). A 1-byte
// one-hot mask has exactly BB nonzero bytes total. Plain stores: idempotent
// across graph replays. Block 0 also resets the forward completion counter.
// ---------------------------------------------------------------------------
__global__ __launch_bounds__(256) void detect_kernel(const unsigned char* __restrict__ m)
{
    __shared__ int w_s[8];
    const int tid = threadIdx.x;
    if (blockIdx.x == 0 && tid == 0) g_done = 0;
    uint4 v = ((const uint4*)m)[blockIdx.x * 256 + tid];
    int local = CNTB(v.x) + CNTB(v.y) + CNTB(v.z) + CNTB(v.w);
    #pragma unroll
    for (int o = 16; o > 0; o >>= 1) local += __shfl_xor_sync(0xffffffffu, local, o);
    if ((tid & 31) == 0) w_s[tid >> 5] = local;
    __syncthreads();
    if (tid == 0) {
        int s = 0;
        #pragma unroll
        for (int k = 0; k < 8; k++) s += w_s[k];
        g_cntp[blockIdx.x] = s;
    }
}

// ---------------------------------------------------------------------------
// Forward: one CTA (64 threads = 2 warps) per batch element b; thread j owns
// state-column j. Linear-domain recurrence, EXPONENT-ONLY pivot renorm:
//   S_j  = sum_i P_i * E_ij        (E = exp(trans), column j packed f32x2)
//   eb   = exponent field of P_0^{t-1} (integer ops, no MUFU)
//   c    = 2^(127-eb-? ) = __int_as_float((254-eb)<<23)  -- EXACT power of 2
//   P'_j = S_j * em_j * c ;  C2i += eb   (exact integer accumulation)
// Invariant: log2 alpha_j = lg2(P_j) + (C2i - 127*t)  (exact).
// t-loop unrolled x4, static buffer roles; ex2 emit conversion after the bar.
// Final per-b: LN2*((C2i-127*stop) + lg2(sum_j P_j)). Last CTA does 512->1.
// ---------------------------------------------------------------------------
__global__ __launch_bounds__(KK, 8)
void crf_forward_kernel(const float* __restrict__ emits,
                        const unsigned char* __restrict__ mask,
                        const float* __restrict__ trans,
                        const float* __restrict__ alpha0,
                        float* __restrict__ out)
{
    __shared__ float p_s[2][KK];
    __shared__ float red_s[2];
    __shared__ int   stop_sh;
    __shared__ int   is4_sh;
    __shared__ int   last_s;

    const int j = threadIdx.x;
    const int b = blockIdx.x;

    if (j == 0) stop_sh = 0;

    // mask dtype: sum the 64 detect partials (warp0 lanes load one each)
    if (j < 32) {
        int c0 = g_cntp[j] + g_cntp[j + 32];
        #pragma unroll
        for (int o = 16; o > 0; o >>= 1) c0 += __shfl_xor_sync(0xffffffffu, c0, o);
        if (j == 0) is4_sh = (c0 != BB);
    }
    __syncthreads();
    const bool is4 = is4_sh;

    // stop index: one-hot => exactly one thread fires the atomic
    if (is4) {
        const unsigned* m4 = (const unsigned*)mask;
        #pragma unroll
        for (int k = 0; k < TT / KK; k++) {
            int t = j + KK * k;
            if (m4[t * BB + b]) atomicMax(&stop_sh, t);
        }
    } else {
        #pragma unroll
        for (int k = 0; k < TT / KK; k++) {
            int t = j + KK * k;
            if (mask[t * BB + b]) atomicMax(&stop_sh, t);
        }
    }

    // E = exp(trans) column j, packed over i-pairs (register-resident)
    ull tr2[KK / 2];
    #pragma unroll
    for (int m = 0; m < KK / 2; m++)
        tr2[m] = pack2_(ex2f_(trans[(2*m  )*KK + j] * LOG2E),
                        ex2f_(trans[(2*m+1)*KK + j] * LOG2E));

    __syncthreads();
    const int stop = stop_sh;   // uniform

    const float* ep = emits + b * KK + j;
    float P = ex2f_((alpha0[j] + ep[0]) * LOG2E);
    p_s[0][j] = P;
    int C2i = 0;                // sum of biased exponents of the pivots (exact)

    // emit pipeline depth 4: em = converted emit(t); rA,rB,rC = raw emit(t+1..t+3)
    float em = ex2f_(ep[min(1, stop) * STRD] * LOG2E);
    float rA = ep[min(2, stop) * STRD];
    float rB = ep[min(3, stop) * STRD];
    float rC = ep[min(4, stop) * STRD];

    __syncthreads();

    // One recurrence step. Read p_s[RB], write p_s[WB] (static indices).
    // EMIT = converted emit(t). LDREG <- raw emit(t+4) (min-clamped; clamped
    // reads duplicate emit(stop) which is never consumed). NEWEM = ex2 of raw
    // emit(t+1), issued AFTER the barrier (private regs, not defer-blocked).
#define CRF_STEP(RB, WB, TCUR, EMIT, RNEXT, LDREG, NEWEM)                      \
    {                                                                          \
        const float LDREG = ep[(long)min((TCUR) + 4, stop) * STRD];            \
        const ulonglong2* p2 = (const ulonglong2*)p_s[RB];                     \
        ulonglong2 v0 = p2[0];                                                 \
        const int eb = ((int)(__float_as_uint(unpack2_(v0.x).x) >> 23));       \
        C2i += eb;                                   /* exact, ALU pipe */     \
        const float c = __int_as_float((254 - eb) << 23);  /* exact 2^-e */    \
        const float emc = (EMIT) * c;                                          \
        ull a0 = fma2_(v0.x, tr2[0], 0ull);                                    \
        ull a1 = fma2_(v0.y, tr2[1], 0ull);                                    \
        ulonglong2 w0 = p2[1];                                                 \
        ull a2 = fma2_(w0.x, tr2[2], 0ull);                                    \
        ull a3 = fma2_(w0.y, tr2[3], 0ull);                                    \
        ulonglong2 v1 = p2[2];                                                 \
        ull a4 = fma2_(v1.x, tr2[4], 0ull);                                    \
        ull a5 = fma2_(v1.y, tr2[5], 0ull);                                    \
        ulonglong2 w1 = p2[3];                                                 \
        ull a6 = fma2_(w1.x, tr2[6], 0ull);                                    \
        ull a7 = fma2_(w1.y, tr2[7], 0ull);                                    \
        _Pragma("unroll")                                                      \
        for (int i = 2; i < 8; i++) {                                          \
            ulonglong2 v = p2[2*i], w = p2[2*i+1];                             \
            a0 = fma2_(v.x, tr2[4*i+0], a0);                                   \
            a1 = fma2_(v.y, tr2[4*i+1], a1);                                   \
            a2 = fma2_(w.x, tr2[4*i+2], a2);                                   \
            a3 = fma2_(w.y, tr2[4*i+3], a3);                                   \
        }                                                                      \
        ull s01 = add2_(a0, a1), s23 = add2_(a2, a3);                          \
        ull s45 = add2_(a4, a5), s67 = add2_(a6, a7);                          \
        float2 f = unpack2_(add2_(add2_(s01, s23), add2_(s45, s67)));          \
        const float S = f.x + f.y;                                             \
        P = S * emc;                                                           \
        p_s[WB][j] = P;                                                        \
        __syncthreads();                                                       \
        const float NEWEM = ex2f_((RNEXT) * LOG2E);  /* post-bar: private */   \
        (void)NEWEM;

#define CRF_END }

    int t = 1;
    for (; t + 3 <= stop; t += 4) {
        CRF_STEP(0, 1, t,     em,  rA, ld0, em1)
        CRF_STEP(1, 0, t + 1, em1, rB, ld1, em2)
        CRF_STEP(0, 1, t + 2, em2, rC, ld2, em3)
        CRF_STEP(1, 0, t + 3, em3, ld0, ld3, em4)
        em = em4; rA = ld1; rB = ld2; rC = ld3;
        CRF_END CRF_END CRF_END CRF_END
    }
    for (; t <= stop; t++) {
        if ((t & 1) == 1) {
            CRF_STEP(0, 1, t, em, rA, lde, eme)
            em = eme; rA = rB; rB = rC; rC = lde;
            CRF_END
        } else {
            CRF_STEP(1, 0, t, em, rA, lde, eme)
            em = eme; rA = rB; rB = rC; rC = lde;
            CRF_END
        }
    }
#undef CRF_STEP
#undef CRF_END

    // per-b sum over states -> logZ_b
    float v = P;
    #pragma unroll
    for (int o = 16; o > 0; o >>= 1) v += __shfl_xor_sync(0xffffffffu, v, o);
    if ((j & 31) == 0) red_s[j >> 5] = v;
    __syncthreads();
    if (j == 0) {
        const float C2 = (float)(C2i - 127 * stop);  // de-bias the exponents
        g_partial[b] = LN2 * (C2 + lg2f_(red_s[0] + red_s[1]));
        __threadfence();
        last_s = (atomicAdd(&g_done, 1) == BB - 1);
    }
    __syncthreads();

    if (last_s) {                                    // deterministic 512->1 sum
        __threadfence();
        float s = 0.f;
        #pragma unroll
        for (int k = 0; k < BB / KK; k++) s += g_partial[j + k * KK];
        #pragma unroll
        for (int o = 16; o > 0; o >>= 1) s += __shfl_xor_sync(0xffffffffu, s, o);
        if ((j & 31) == 0) red_s[j >> 5] = s;
        __syncthreads();
        if (j == 0) out[0] = red_s[0] + red_s[1];
    }
}

extern "C" void kernel_launch(void* const* d_in, const int* in_sizes, int n_in,
                              void* d_out, int out_size)
{
    // Identify inputs by element count (robust to metadata ordering):
    // emits 16777216, mask 262144, trans 4096, alpha0 64.
    const float*         emits  = 0;
    const unsigned char* mask   = 0;
    const float*         trans  = 0;
    const float*         alpha0 = 0;
    for (int i = 0; i < n_in; i++) {
        switch (in_sizes[i]) {
            case 16777216: emits  = (const float*)d_in[i];         break;
            case   262144: mask   = (const unsigned char*)d_in[i]; break;
            case     4096: trans  = (const float*)d_in[i];         break;
            case       64: alpha0 = (const float*)d_in[i];         break;
        }
    }
    detect_kernel<<<64, 256>>>(mask);
    crf_forward_kernel<<<BB, KK>>>(emits, mask, trans, alpha0, (float*)d_out);
}